// round 11
// baseline (speedup 1.0000x reference)
#include <cuda_runtime.h>
#include <cuda_fp16.h>
#include <cstdint>
#include <cstddef>

// ---------------------------------------------------------------------------
// B=16, S=1024, DIM=768, H=12, HD=64 — fp16 tensor-core pipeline:
//   qkv(fp16) = x @ W_attn + b_attn    (fp16 MMA, fp32 accum, 128x256 tile)
//   attn      = causal MHA             (fp16 MMA, static-max softmax, KV-64)
//   out       = attn @ W_proj + b_proj (fp16 MMA, fp32 out)
// ---------------------------------------------------------------------------
#define BATCH 16
#define SEQ   1024
#define DIM   768
#define NH    12
#define HD    64
#define MROWS (BATCH * SEQ)
#define KTOT  768
#define N1    (3 * DIM)
#define N2    DIM

__device__ __half g_qkv16[MROWS * N1];
__device__ __half g_x16[MROWS * KTOT];
__device__ __half g_a16[MROWS * KTOT];
__device__ __half g_w1[N1 * KTOT];
__device__ __half g_w2[N2 * KTOT];

// ============================ PTX helpers ==================================
__device__ __forceinline__ uint32_t smem_u32(const void* p) {
    uint32_t a;
    asm("{ .reg .u64 t; cvta.to.shared.u64 t, %1; cvt.u32.u64 %0, t; }"
        : "=r"(a) : "l"(p));
    return a;
}

#define CP16(d, s) \
    asm volatile("cp.async.cg.shared.global [%0], [%1], 16;" :: "r"(d), "l"(s))
#define CP_COMMIT() asm volatile("cp.async.commit_group;" ::: "memory")
#define CP_WAIT(n)  asm volatile("cp.async.wait_group %0;" :: "n"(n) : "memory")

#define LDSM4(r0, r1, r2, r3, a) \
    asm volatile("ldmatrix.sync.aligned.m8n8.x4.shared.b16 {%0,%1,%2,%3}, [%4];" \
                 : "=r"(r0), "=r"(r1), "=r"(r2), "=r"(r3) : "r"(a))

#define LDSM4T(r0, r1, r2, r3, a) \
    asm volatile("ldmatrix.sync.aligned.m8n8.x4.trans.shared.b16 {%0,%1,%2,%3}, [%4];" \
                 : "=r"(r0), "=r"(r1), "=r"(r2), "=r"(r3) : "r"(a))

#define MMA_F16(d, a0, a1, a2, a3, b0, b1) \
    asm volatile("mma.sync.aligned.m16n8k16.row.col.f32.f16.f16.f32 " \
                 "{%0,%1,%2,%3}, {%4,%5,%6,%7}, {%8,%9}, {%0,%1,%2,%3};" \
                 : "+f"((d)[0]), "+f"((d)[1]), "+f"((d)[2]), "+f"((d)[3]) \
                 : "r"(a0), "r"(a1), "r"(a2), "r"(a3), "r"(b0), "r"(b1))

__device__ __forceinline__ uint32_t pack_h(float x, float y) {
    __half2 t = __float22half2_rn(make_float2(x, y));
    return *(uint32_t*)&t;
}

// ======================= conversion kernels ================================
__global__ __launch_bounds__(256) void cvt_f16(
    const float* __restrict__ in, __half* __restrict__ out, int n4)
{
    int i = blockIdx.x * 256 + threadIdx.x;
    if (i >= n4) return;
    float4 v = ((const float4*)in)[i];
    ((uint32_t*)out)[i * 2 + 0] = pack_h(v.x, v.y);
    ((uint32_t*)out)[i * 2 + 1] = pack_h(v.z, v.w);
}

__global__ __launch_bounds__(256) void transpose_f16(
    const float* __restrict__ W, __half* __restrict__ T, int K, int N)
{
    __shared__ float tile[32][33];
    int tx = threadIdx.x, ty = threadIdx.y;
    int nx = blockIdx.x * 32 + tx;
    int ky = blockIdx.y * 32 + ty;
    #pragma unroll
    for (int j = 0; j < 32; j += 8)
        tile[ty + j][tx] = W[(size_t)(ky + j) * N + nx];
    __syncthreads();
    int kx = blockIdx.y * 32 + tx;
    int ny = blockIdx.x * 32 + ty;
    #pragma unroll
    for (int j = 0; j < 32; j += 8)
        T[(size_t)(ny + j) * K + kx] = __float2half(tile[tx][ty + j]);
}

// ================== HMMA GEMM (single-term fp16) ===========================
// 128x256 tile, BK=64, 3 stages x 48KB, 256 threads (8 warps, 32x128 each).
#define NSTG    3
#define NIT     12
#define T_A     0
#define T_B     16384
#define STG     49152
#define GEMM_SMEM (NSTG * STG)     // 147456

__device__ __forceinline__ void stage_load(
    uint32_t sstage, const __half* A, const __half* B,
    int mtile, int ntile, int kiter, int tid)
{
    #pragma unroll
    for (int j = 0; j < 4; j++) {              // A: 128 rows x 8 chunks
        int idx = tid + j * 256;
        int r = idx >> 3, c = idx & 7;
        uint32_t so = (uint32_t)(r * 128 + ((c ^ (r & 7)) << 4));
        CP16(sstage + T_A + so,
             (const char*)(A + (size_t)(mtile * 128 + r) * KTOT + kiter * 64 + c * 8));
    }
    #pragma unroll
    for (int j = 0; j < 8; j++) {              // B: 256 rows x 8 chunks
        int idx = tid + j * 256;
        int r = idx >> 3, c = idx & 7;
        uint32_t so = (uint32_t)(r * 128 + ((c ^ (r & 7)) << 4));
        CP16(sstage + T_B + so,
             (const char*)(B + (size_t)(ntile * 256 + r) * KTOT + kiter * 64 + c * 8));
    }
}

template<int OUT16>
__global__ __launch_bounds__(256) void gemm_mma(
    const __half* __restrict__ A, const __half* __restrict__ B,
    const float* __restrict__ bias, float* __restrict__ Cf,
    __half* __restrict__ Ch, int Ntot)
{
    extern __shared__ char smem[];
    const uint32_t sb = smem_u32(smem);
    const int tid = threadIdx.x, lane = tid & 31, wid = tid >> 5;
    const int mtile = blockIdx.y, ntile = blockIdx.x;
    const int wm = (wid & 3) * 32;         // 4 m-groups
    const int wn = (wid >> 2) * 128;       // 2 n-groups

    const int rowA  = wm + (lane & 15);
    const int xorA  = rowA & 7;
    const int clA   = lane >> 4;
    const int rowB  = wn + ((lane >> 4) << 3) + (lane & 7);
    const int xorB  = rowB & 7;
    const int clB   = (lane >> 3) & 1;

    float acc[2][16][4];
    #pragma unroll
    for (int mf = 0; mf < 2; mf++)
        #pragma unroll
        for (int nf = 0; nf < 16; nf++)
            #pragma unroll
            for (int q = 0; q < 4; q++) acc[mf][nf][q] = 0.f;

    stage_load(sb + 0 * STG, A, B, mtile, ntile, 0, tid); CP_COMMIT();
    stage_load(sb + 1 * STG, A, B, mtile, ntile, 1, tid); CP_COMMIT();

    for (int i = 0; i < NIT; i++) {
        if (i + 1 < NIT) { CP_WAIT(1); } else { CP_WAIT(0); }
        __syncthreads();

        if (i + 2 < NIT) {
            stage_load(sb + ((i + 2) % NSTG) * STG, A, B, mtile, ntile, i + 2, tid);
            CP_COMMIT();
        }

        const uint32_t st = sb + (i % NSTG) * STG;
        #pragma unroll
        for (int ks = 0; ks < 4; ks++) {
            uint32_t ar[2][4], br[16][2];
            #pragma unroll
            for (int mf = 0; mf < 2; mf++) {
                uint32_t off = (uint32_t)((rowA + mf * 16) * 128 +
                               ((((ks << 1) + clA) ^ xorA) << 4));
                LDSM4(ar[mf][0], ar[mf][1], ar[mf][2], ar[mf][3], st + T_A + off);
            }
            #pragma unroll
            for (int nf2 = 0; nf2 < 8; nf2++) {
                uint32_t off = (uint32_t)((rowB + nf2 * 16) * 128 +
                               ((((ks << 1) + clB) ^ xorB) << 4));
                LDSM4(br[nf2 * 2][0], br[nf2 * 2][1],
                      br[nf2 * 2 + 1][0], br[nf2 * 2 + 1][1], st + T_B + off);
            }
            #pragma unroll
            for (int mf = 0; mf < 2; mf++)
                #pragma unroll
                for (int nf = 0; nf < 16; nf++)
                    MMA_F16(acc[mf][nf], ar[mf][0], ar[mf][1], ar[mf][2], ar[mf][3],
                            br[nf][0], br[nf][1]);
        }
    }

    #pragma unroll
    for (int mf = 0; mf < 2; mf++) {
        #pragma unroll
        for (int nf = 0; nf < 16; nf++) {
            const int col = ntile * 256 + wn + nf * 8 + (lane & 3) * 2;
            const int row0 = mtile * 128 + wm + mf * 16 + (lane >> 2);
            const float b0 = bias[col], b1 = bias[col + 1];
            float v0 = acc[mf][nf][0] + b0, v1 = acc[mf][nf][1] + b1;
            float v2 = acc[mf][nf][2] + b0, v3 = acc[mf][nf][3] + b1;
            if (OUT16) {
                *(uint32_t*)&Ch[(size_t)row0 * Ntot + col] = pack_h(v0, v1);
                *(uint32_t*)&Ch[(size_t)(row0 + 8) * Ntot + col] = pack_h(v2, v3);
            } else {
                *(float2*)&Cf[(size_t)row0 * Ntot + col] = make_float2(v0, v1);
                *(float2*)&Cf[(size_t)(row0 + 8) * Ntot + col] = make_float2(v2, v3);
            }
        }
    }
}

// ============== tensor-core causal flash attention (fp16) ==================
// CTA: 128 q-rows x 1 head, 8 warps, KV-tile 64, 3-stage KV pipeline.
// Static-max softmax (scores provably small: |s*C1| < ~6).
// smem: Q 16KB + 3 x 16KB = 64KB -> 2 CTAs/SM.
#define AQ_OFF   0
#define ABUF0    16384
#define A_V      8192             // V offset within a stage
#define A_BUF    16384
#define ATT_SMEM 65536
#define C1 0.18033688011112042f   // 0.125 * log2(e)

__device__ __forceinline__ void attn_load_kv(
    uint32_t bufbase, const __half* qkv, int b, int h, int jt, int tid)
{
    #pragma unroll
    for (int j = 0; j < 4; j++) {
        int idx = tid + j * 256;
        if (idx < 512) {
            int r = idx >> 3, c = idx & 7;
            const __half* src = qkv
                + (size_t)(b * SEQ + jt * 64 + r) * N1 + DIM + h * HD + c * 8;
            CP16(bufbase + r * 128 + ((c ^ (r & 7)) << 4), src);
        } else {
            int rem = idx - 512;
            int r = rem >> 3, c = rem & 7;
            const __half* src = qkv
                + (size_t)(b * SEQ + jt * 64 + r) * N1 + 2 * DIM + h * HD + c * 8;
            CP16(bufbase + A_V + r * 128 + ((c ^ (r & 7)) << 4), src);
        }
    }
}

__global__ __launch_bounds__(256, 2) void attn_mma(
    const __half* __restrict__ qkv, __half* __restrict__ outa)
{
    extern __shared__ char smem[];
    const uint32_t sb = smem_u32(smem);
    const int tid = threadIdx.x, lane = tid & 31, w = tid >> 5;
    const int qt = gridDim.x - 1 - blockIdx.x;   // longest-first
    const int h = blockIdx.y, b = blockIdx.z;
    const int nt = 2 * qt + 2;                    // KV tiles of 64 (nt >= 2)

    // ---- stage Q tile (128 x 64), then to fragments ----
    #pragma unroll
    for (int j = 0; j < 4; j++) {
        int idx = tid + j * 256;
        int r = idx >> 3, c = idx & 7;
        const __half* src = qkv
            + (size_t)(b * SEQ + qt * 128 + r) * N1 + h * HD + c * 8;
        CP16(sb + AQ_OFF + r * 128 + ((c ^ (r & 7)) << 4), src);
    }
    CP_COMMIT(); CP_WAIT(0);
    __syncthreads();

    const int rowA = w * 16 + (lane & 15);
    const int clA = lane >> 4, xorA = rowA & 7;
    uint32_t qf[4][4];
    #pragma unroll
    for (int ks = 0; ks < 4; ks++) {
        uint32_t off = (uint32_t)(rowA * 128 + ((((ks << 1) + clA) ^ xorA) << 4));
        LDSM4(qf[ks][0], qf[ks][1], qf[ks][2], qf[ks][3], sb + AQ_OFF + off);
    }

    attn_load_kv(sb + ABUF0, qkv, b, h, 0, tid); CP_COMMIT();
    attn_load_kv(sb + ABUF0 + A_BUF, qkv, b, h, 1, tid); CP_COMMIT();

    float lsum[2] = {0.f, 0.f};
    float o[8][4];
    #pragma unroll
    for (int nf = 0; nf < 8; nf++)
        #pragma unroll
        for (int q = 0; q < 4; q++) o[nf][q] = 0.f;

    const int rowB = ((lane >> 4) << 3) + (lane & 7);
    const int clB = (lane >> 3) & 1, xorB = lane & 7;
    const int vkr = (lane & 7) + ((lane >> 3) & 1) * 8;
    const int vdc = lane >> 4;
    const int r0g = qt * 128 + w * 16 + (lane >> 2);   // global q row (first half)

    for (int jt = 0; jt < nt; jt++) {
        if (jt + 1 < nt) { CP_WAIT(1); } else { CP_WAIT(0); }
        __syncthreads();
        if (jt + 2 < nt) {
            attn_load_kv(sb + ABUF0 + ((jt + 2) % 3) * A_BUF, qkv, b, h, jt + 2, tid);
            CP_COMMIT();
        }
        const uint32_t kb = sb + ABUF0 + (jt % 3) * A_BUF;

        // ---- scores S = Q K^T (16 q-rows x 64 kv per warp) ----
        float s[8][4];
        #pragma unroll
        for (int nf = 0; nf < 8; nf++)
            #pragma unroll
            for (int q = 0; q < 4; q++) s[nf][q] = 0.f;

        #pragma unroll
        for (int ks = 0; ks < 4; ks++) {
            #pragma unroll
            for (int nf2 = 0; nf2 < 4; nf2++) {
                uint32_t off = (uint32_t)((rowB + nf2 * 16) * 128 +
                               ((((ks << 1) + clB) ^ xorB) << 4));
                uint32_t k0, k1, k2, k3;
                LDSM4(k0, k1, k2, k3, kb + off);
                MMA_F16(s[nf2 * 2],     qf[ks][0], qf[ks][1], qf[ks][2], qf[ks][3], k0, k1);
                MMA_F16(s[nf2 * 2 + 1], qf[ks][0], qf[ks][1], qf[ks][2], qf[ks][3], k2, k3);
            }
        }

        // ---- causal mask (tiles overlapping the diagonal) ----
        if (jt >= 2 * qt) {
            #pragma unroll
            for (int nf = 0; nf < 8; nf++) {
                const int c0g = jt * 64 + nf * 8 + (lane & 3) * 2;
                if (c0g     > r0g)     s[nf][0] = -3e38f;
                if (c0g + 1 > r0g)     s[nf][1] = -3e38f;
                if (c0g     > r0g + 8) s[nf][2] = -3e38f;
                if (c0g + 1 > r0g + 8) s[nf][3] = -3e38f;
            }
        }

        // ---- static-max softmax: p = 2^(s*C1); masked -> 2^-inf = 0 ----
        #pragma unroll
        for (int nf = 0; nf < 8; nf++) {
            s[nf][0] = exp2f(s[nf][0] * C1); lsum[0] += s[nf][0];
            s[nf][1] = exp2f(s[nf][1] * C1); lsum[0] += s[nf][1];
            s[nf][2] = exp2f(s[nf][2] * C1); lsum[1] += s[nf][2];
            s[nf][3] = exp2f(s[nf][3] * C1); lsum[1] += s[nf][3];
        }

        // ---- O += P V (P packed fp16 in-register; V via ldmatrix.trans) ----
        #pragma unroll
        for (int kc = 0; kc < 4; kc++) {
            uint32_t pa0 = pack_h(s[2 * kc][0],     s[2 * kc][1]);
            uint32_t pa1 = pack_h(s[2 * kc][2],     s[2 * kc][3]);
            uint32_t pa2 = pack_h(s[2 * kc + 1][0], s[2 * kc + 1][1]);
            uint32_t pa3 = pack_h(s[2 * kc + 1][2], s[2 * kc + 1][3]);
            const int kr = kc * 16 + vkr;
            #pragma unroll
            for (int nf2 = 0; nf2 < 4; nf2++) {
                uint32_t off = (uint32_t)(kr * 128 +
                               (((nf2 * 2 + vdc) ^ (kr & 7)) << 4));
                uint32_t v0, v1, v2, v3;
                LDSM4T(v0, v1, v2, v3, kb + A_V + off);
                MMA_F16(o[nf2 * 2],     pa0, pa1, pa2, pa3, v0, v1);
                MMA_F16(o[nf2 * 2 + 1], pa0, pa1, pa2, pa3, v2, v3);
            }
        }
    }

    // ---- final row-sum reduce (deferred), normalize + write fp16 ----
    lsum[0] += __shfl_xor_sync(0xffffffffu, lsum[0], 1);
    lsum[0] += __shfl_xor_sync(0xffffffffu, lsum[0], 2);
    lsum[1] += __shfl_xor_sync(0xffffffffu, lsum[1], 1);
    lsum[1] += __shfl_xor_sync(0xffffffffu, lsum[1], 2);
    const float inv0 = 1.f / lsum[0], inv1 = 1.f / lsum[1];
    const size_t gr = (size_t)(b * SEQ + qt * 128 + w * 16 + (lane >> 2));
    const int colb = h * HD + (lane & 3) * 2;
    #pragma unroll
    for (int nf = 0; nf < 8; nf++) {
        const int col = colb + nf * 8;
        *(uint32_t*)&outa[gr * DIM + col] = pack_h(o[nf][0] * inv0, o[nf][1] * inv0);
        *(uint32_t*)&outa[(gr + 8) * DIM + col] = pack_h(o[nf][2] * inv1, o[nf][3] * inv1);
    }
}

// =============================== launch ====================================
extern "C" void kernel_launch(void* const* d_in, const int* in_sizes, int n_in,
                              void* d_out, int out_size)
{
    const float* x      = (const float*)d_in[0];
    const float* W_attn = (const float*)d_in[1];
    const float* b_attn = (const float*)d_in[2];
    const float* W_proj = (const float*)d_in[3];
    const float* b_proj = (const float*)d_in[4];
    float* out = (float*)d_out;

    __half *qkv16, *x16, *a16, *w1, *w2;
    cudaGetSymbolAddress((void**)&qkv16, g_qkv16);
    cudaGetSymbolAddress((void**)&x16, g_x16);
    cudaGetSymbolAddress((void**)&a16, g_a16);
    cudaGetSymbolAddress((void**)&w1, g_w1);
    cudaGetSymbolAddress((void**)&w2, g_w2);

    static int attrs_set = 0;
    if (!attrs_set) {
        cudaFuncSetAttribute(gemm_mma<0>, cudaFuncAttributeMaxDynamicSharedMemorySize, GEMM_SMEM);
        cudaFuncSetAttribute(gemm_mma<1>, cudaFuncAttributeMaxDynamicSharedMemorySize, GEMM_SMEM);
        cudaFuncSetAttribute(attn_mma, cudaFuncAttributeMaxDynamicSharedMemorySize, ATT_SMEM);
        attrs_set = 1;
    }

    // 1) x -> fp16
    {
        int n4 = MROWS * KTOT / 4;
        cvt_f16<<<(n4 + 255) / 256, 256>>>(x, x16, n4);
    }
    // 2) weights -> transposed fp16
    transpose_f16<<<dim3(N1 / 32, KTOT / 32), dim3(32, 8)>>>(W_attn, w1, KTOT, N1);
    transpose_f16<<<dim3(N2 / 32, KTOT / 32), dim3(32, 8)>>>(W_proj, w2, KTOT, N2);
    // 3) qkv GEMM (fp16 out)
    gemm_mma<1><<<dim3(N1 / 256, MROWS / 128), 256, GEMM_SMEM>>>(
        x16, w1, b_attn, nullptr, qkv16, N1);
    // 4) attention
    attn_mma<<<dim3(SEQ / 128, NH, BATCH), 256, ATT_SMEM>>>(qkv16, a16);
    // 5) out GEMM (fp32 out)
    gemm_mma<0><<<dim3(N2 / 256, MROWS / 128), 256, GEMM_SMEM>>>(
        a16, w2, b_proj, out, nullptr, N2);
}

// round 12
// speedup vs baseline: 1.0405x; 1.0405x over previous
#include <cuda_runtime.h>
#include <cuda_fp16.h>
#include <cstdint>
#include <cstddef>

// ---------------------------------------------------------------------------
// B=16, S=1024, DIM=768, H=12, HD=64 — fp16 tensor-core pipeline:
//   qkv(fp16) = x @ W_attn + b_attn    (fp16 MMA, fp32 accum, 128x128 tile)
//   attn      = causal MHA             (fp16 MMA, static-max softmax, KV-64, 3-stage)
//   out       = attn @ W_proj + b_proj (fp16 MMA, fp32 out)
// ---------------------------------------------------------------------------
#define BATCH 16
#define SEQ   1024
#define DIM   768
#define NH    12
#define HD    64
#define MROWS (BATCH * SEQ)
#define KTOT  768
#define N1    (3 * DIM)
#define N2    DIM

__device__ __half g_qkv16[MROWS * N1];
__device__ __half g_x16[MROWS * KTOT];
__device__ __half g_a16[MROWS * KTOT];
__device__ __half g_w1[N1 * KTOT];
__device__ __half g_w2[N2 * KTOT];

// ============================ PTX helpers ==================================
__device__ __forceinline__ uint32_t smem_u32(const void* p) {
    uint32_t a;
    asm("{ .reg .u64 t; cvta.to.shared.u64 t, %1; cvt.u32.u64 %0, t; }"
        : "=r"(a) : "l"(p));
    return a;
}

#define CP16(d, s) \
    asm volatile("cp.async.cg.shared.global [%0], [%1], 16;" :: "r"(d), "l"(s))
#define CP_COMMIT() asm volatile("cp.async.commit_group;" ::: "memory")
#define CP_WAIT(n)  asm volatile("cp.async.wait_group %0;" :: "n"(n) : "memory")

#define LDSM4(r0, r1, r2, r3, a) \
    asm volatile("ldmatrix.sync.aligned.m8n8.x4.shared.b16 {%0,%1,%2,%3}, [%4];" \
                 : "=r"(r0), "=r"(r1), "=r"(r2), "=r"(r3) : "r"(a))

#define LDSM4T(r0, r1, r2, r3, a) \
    asm volatile("ldmatrix.sync.aligned.m8n8.x4.trans.shared.b16 {%0,%1,%2,%3}, [%4];" \
                 : "=r"(r0), "=r"(r1), "=r"(r2), "=r"(r3) : "r"(a))

#define MMA_F16(d, a0, a1, a2, a3, b0, b1) \
    asm volatile("mma.sync.aligned.m16n8k16.row.col.f32.f16.f16.f32 " \
                 "{%0,%1,%2,%3}, {%4,%5,%6,%7}, {%8,%9}, {%0,%1,%2,%3};" \
                 : "+f"((d)[0]), "+f"((d)[1]), "+f"((d)[2]), "+f"((d)[3]) \
                 : "r"(a0), "r"(a1), "r"(a2), "r"(a3), "r"(b0), "r"(b1))

__device__ __forceinline__ uint32_t pack_h(float x, float y) {
    __half2 t = __float22half2_rn(make_float2(x, y));
    return *(uint32_t*)&t;
}

// ======================= conversion kernels ================================
__global__ __launch_bounds__(256) void cvt_f16(
    const float* __restrict__ in, __half* __restrict__ out, int n4)
{
    int i = blockIdx.x * 256 + threadIdx.x;
    if (i >= n4) return;
    float4 v = ((const float4*)in)[i];
    ((uint32_t*)out)[i * 2 + 0] = pack_h(v.x, v.y);
    ((uint32_t*)out)[i * 2 + 1] = pack_h(v.z, v.w);
}

__global__ __launch_bounds__(256) void transpose_f16(
    const float* __restrict__ W, __half* __restrict__ T, int K, int N)
{
    __shared__ float tile[32][33];
    int tx = threadIdx.x, ty = threadIdx.y;
    int nx = blockIdx.x * 32 + tx;
    int ky = blockIdx.y * 32 + ty;
    #pragma unroll
    for (int j = 0; j < 32; j += 8)
        tile[ty + j][tx] = W[(size_t)(ky + j) * N + nx];
    __syncthreads();
    int kx = blockIdx.y * 32 + tx;
    int ny = blockIdx.x * 32 + ty;
    #pragma unroll
    for (int j = 0; j < 32; j += 8)
        T[(size_t)(ny + j) * K + kx] = __float2half(tile[tx][ty + j]);
}

// ================== HMMA GEMM (single-term fp16) ===========================
// R10-proven config: 128x128 tile, BK=64, 3 stages x 32KB, 256 threads,
// 2 CTAs/SM; per-iter: WAIT -> sync -> issue load(i+2) -> compute(i).
#define NSTG    3
#define NIT     12
#define T_A     0
#define T_B     16384
#define STG     32768
#define GEMM_SMEM (NSTG * STG)     // 98304

__device__ __forceinline__ void stage_load(
    uint32_t sstage, const __half* A, const __half* B,
    int mtile, int ntile, int kiter, int tid)
{
    #pragma unroll
    for (int j = 0; j < 4; j++) {
        int idx = tid + j * 256;
        int r = idx >> 3, c = idx & 7;
        uint32_t so = (uint32_t)(r * 128 + ((c ^ (r & 7)) << 4));
        CP16(sstage + T_A + so,
             (const char*)(A + (size_t)(mtile * 128 + r) * KTOT + kiter * 64 + c * 8));
        CP16(sstage + T_B + so,
             (const char*)(B + (size_t)(ntile * 128 + r) * KTOT + kiter * 64 + c * 8));
    }
}

template<int OUT16>
__global__ __launch_bounds__(256, 2) void gemm_mma(
    const __half* __restrict__ A, const __half* __restrict__ B,
    const float* __restrict__ bias, float* __restrict__ Cf,
    __half* __restrict__ Ch, int Ntot)
{
    extern __shared__ char smem[];
    const uint32_t sb = smem_u32(smem);
    const int tid = threadIdx.x, lane = tid & 31, wid = tid >> 5;
    const int mtile = blockIdx.y, ntile = blockIdx.x;
    const int wm = (wid & 3) * 32;
    const int wn = (wid >> 2) * 64;

    const int rowA  = wm + (lane & 15);
    const int xorA  = rowA & 7;
    const int clA   = lane >> 4;
    const int rowB  = wn + ((lane >> 4) << 3) + (lane & 7);
    const int xorB  = rowB & 7;
    const int clB   = (lane >> 3) & 1;

    float acc[2][8][4];
    #pragma unroll
    for (int mf = 0; mf < 2; mf++)
        #pragma unroll
        for (int nf = 0; nf < 8; nf++)
            #pragma unroll
            for (int q = 0; q < 4; q++) acc[mf][nf][q] = 0.f;

    stage_load(sb + 0 * STG, A, B, mtile, ntile, 0, tid); CP_COMMIT();
    stage_load(sb + 1 * STG, A, B, mtile, ntile, 1, tid); CP_COMMIT();

    for (int i = 0; i < NIT; i++) {
        if (i + 1 < NIT) { CP_WAIT(1); } else { CP_WAIT(0); }
        __syncthreads();

        if (i + 2 < NIT) {
            stage_load(sb + ((i + 2) % NSTG) * STG, A, B, mtile, ntile, i + 2, tid);
            CP_COMMIT();
        }

        const uint32_t st = sb + (i % NSTG) * STG;
        #pragma unroll
        for (int ks = 0; ks < 4; ks++) {
            uint32_t ar[2][4], br[8][2];
            #pragma unroll
            for (int mf = 0; mf < 2; mf++) {
                uint32_t off = (uint32_t)((rowA + mf * 16) * 128 +
                               ((((ks << 1) + clA) ^ xorA) << 4));
                LDSM4(ar[mf][0], ar[mf][1], ar[mf][2], ar[mf][3], st + T_A + off);
            }
            #pragma unroll
            for (int nf2 = 0; nf2 < 4; nf2++) {
                uint32_t off = (uint32_t)((rowB + nf2 * 16) * 128 +
                               ((((ks << 1) + clB) ^ xorB) << 4));
                LDSM4(br[nf2 * 2][0], br[nf2 * 2][1],
                      br[nf2 * 2 + 1][0], br[nf2 * 2 + 1][1], st + T_B + off);
            }
            #pragma unroll
            for (int mf = 0; mf < 2; mf++)
                #pragma unroll
                for (int nf = 0; nf < 8; nf++)
                    MMA_F16(acc[mf][nf], ar[mf][0], ar[mf][1], ar[mf][2], ar[mf][3],
                            br[nf][0], br[nf][1]);
        }
    }

    #pragma unroll
    for (int mf = 0; mf < 2; mf++) {
        #pragma unroll
        for (int nf = 0; nf < 8; nf++) {
            const int col = ntile * 128 + wn + nf * 8 + (lane & 3) * 2;
            const int row0 = mtile * 128 + wm + mf * 16 + (lane >> 2);
            const float b0 = bias[col], b1 = bias[col + 1];
            float v0 = acc[mf][nf][0] + b0, v1 = acc[mf][nf][1] + b1;
            float v2 = acc[mf][nf][2] + b0, v3 = acc[mf][nf][3] + b1;
            if (OUT16) {
                *(uint32_t*)&Ch[(size_t)row0 * Ntot + col] = pack_h(v0, v1);
                *(uint32_t*)&Ch[(size_t)(row0 + 8) * Ntot + col] = pack_h(v2, v3);
            } else {
                *(float2*)&Cf[(size_t)row0 * Ntot + col] = make_float2(v0, v1);
                *(float2*)&Cf[(size_t)(row0 + 8) * Ntot + col] = make_float2(v2, v3);
            }
        }
    }
}

// ============== tensor-core causal flash attention (fp16) ==================
// CTA: 128 q-rows x 1 head, 8 warps, KV-tile 64, 3-stage KV pipeline.
// Static-max softmax (scores provably small: |s*C1| < ~6).
// smem: Q 16KB + 3 x 16KB = 64KB -> 2 CTAs/SM.
#define AQ_OFF   0
#define ABUF0    16384
#define A_V      8192             // V offset within a stage
#define A_BUF    16384
#define ATT_SMEM 65536
#define C1 0.18033688011112042f   // 0.125 * log2(e)

__device__ __forceinline__ void attn_load_kv(
    uint32_t bufbase, const __half* qkv, int b, int h, int jt, int tid)
{
    #pragma unroll
    for (int j = 0; j < 4; j++) {
        int idx = tid + j * 256;
        if (idx < 512) {
            int r = idx >> 3, c = idx & 7;
            const __half* src = qkv
                + (size_t)(b * SEQ + jt * 64 + r) * N1 + DIM + h * HD + c * 8;
            CP16(bufbase + r * 128 + ((c ^ (r & 7)) << 4), src);
        } else {
            int rem = idx - 512;
            int r = rem >> 3, c = rem & 7;
            const __half* src = qkv
                + (size_t)(b * SEQ + jt * 64 + r) * N1 + 2 * DIM + h * HD + c * 8;
            CP16(bufbase + A_V + r * 128 + ((c ^ (r & 7)) << 4), src);
        }
    }
}

__global__ __launch_bounds__(256, 2) void attn_mma(
    const __half* __restrict__ qkv, __half* __restrict__ outa)
{
    extern __shared__ char smem[];
    const uint32_t sb = smem_u32(smem);
    const int tid = threadIdx.x, lane = tid & 31, w = tid >> 5;
    const int qt = gridDim.x - 1 - blockIdx.x;   // longest-first
    const int h = blockIdx.y, b = blockIdx.z;
    const int nt = 2 * qt + 2;                    // KV tiles of 64 (nt >= 2)

    // ---- stage Q tile (128 x 64), then to fragments ----
    #pragma unroll
    for (int j = 0; j < 4; j++) {
        int idx = tid + j * 256;
        int r = idx >> 3, c = idx & 7;
        const __half* src = qkv
            + (size_t)(b * SEQ + qt * 128 + r) * N1 + h * HD + c * 8;
        CP16(sb + AQ_OFF + r * 128 + ((c ^ (r & 7)) << 4), src);
    }
    CP_COMMIT(); CP_WAIT(0);
    __syncthreads();

    const int rowA = w * 16 + (lane & 15);
    const int clA = lane >> 4, xorA = rowA & 7;
    uint32_t qf[4][4];
    #pragma unroll
    for (int ks = 0; ks < 4; ks++) {
        uint32_t off = (uint32_t)(rowA * 128 + ((((ks << 1) + clA) ^ xorA) << 4));
        LDSM4(qf[ks][0], qf[ks][1], qf[ks][2], qf[ks][3], sb + AQ_OFF + off);
    }

    attn_load_kv(sb + ABUF0, qkv, b, h, 0, tid); CP_COMMIT();
    attn_load_kv(sb + ABUF0 + A_BUF, qkv, b, h, 1, tid); CP_COMMIT();

    float lsum[2] = {0.f, 0.f};
    float o[8][4];
    #pragma unroll
    for (int nf = 0; nf < 8; nf++)
        #pragma unroll
        for (int q = 0; q < 4; q++) o[nf][q] = 0.f;

    const int rowB = ((lane >> 4) << 3) + (lane & 7);
    const int clB = (lane >> 3) & 1, xorB = lane & 7;
    const int vkr = (lane & 7) + ((lane >> 3) & 1) * 8;
    const int vdc = lane >> 4;
    const int r0g = qt * 128 + w * 16 + (lane >> 2);   // global q row (first half)

    for (int jt = 0; jt < nt; jt++) {
        if (jt + 1 < nt) { CP_WAIT(1); } else { CP_WAIT(0); }
        __syncthreads();
        if (jt + 2 < nt) {
            attn_load_kv(sb + ABUF0 + ((jt + 2) % 3) * A_BUF, qkv, b, h, jt + 2, tid);
            CP_COMMIT();
        }
        const uint32_t kb = sb + ABUF0 + (jt % 3) * A_BUF;

        // ---- scores S = Q K^T (16 q-rows x 64 kv per warp) ----
        float s[8][4];
        #pragma unroll
        for (int nf = 0; nf < 8; nf++)
            #pragma unroll
            for (int q = 0; q < 4; q++) s[nf][q] = 0.f;

        #pragma unroll
        for (int ks = 0; ks < 4; ks++) {
            #pragma unroll
            for (int nf2 = 0; nf2 < 4; nf2++) {
                uint32_t off = (uint32_t)((rowB + nf2 * 16) * 128 +
                               ((((ks << 1) + clB) ^ xorB) << 4));
                uint32_t k0, k1, k2, k3;
                LDSM4(k0, k1, k2, k3, kb + off);
                MMA_F16(s[nf2 * 2],     qf[ks][0], qf[ks][1], qf[ks][2], qf[ks][3], k0, k1);
                MMA_F16(s[nf2 * 2 + 1], qf[ks][0], qf[ks][1], qf[ks][2], qf[ks][3], k2, k3);
            }
        }

        // ---- causal mask (tiles overlapping the diagonal) ----
        if (jt >= 2 * qt) {
            #pragma unroll
            for (int nf = 0; nf < 8; nf++) {
                const int c0g = jt * 64 + nf * 8 + (lane & 3) * 2;
                if (c0g     > r0g)     s[nf][0] = -3e38f;
                if (c0g + 1 > r0g)     s[nf][1] = -3e38f;
                if (c0g     > r0g + 8) s[nf][2] = -3e38f;
                if (c0g + 1 > r0g + 8) s[nf][3] = -3e38f;
            }
        }

        // ---- static-max softmax: p = 2^(s*C1); masked -> 0 ----
        #pragma unroll
        for (int nf = 0; nf < 8; nf++) {
            s[nf][0] = exp2f(s[nf][0] * C1); lsum[0] += s[nf][0];
            s[nf][1] = exp2f(s[nf][1] * C1); lsum[0] += s[nf][1];
            s[nf][2] = exp2f(s[nf][2] * C1); lsum[1] += s[nf][2];
            s[nf][3] = exp2f(s[nf][3] * C1); lsum[1] += s[nf][3];
        }

        // ---- O += P V (P packed fp16 in-register; V via ldmatrix.trans) ----
        #pragma unroll
        for (int kc = 0; kc < 4; kc++) {
            uint32_t pa0 = pack_h(s[2 * kc][0],     s[2 * kc][1]);
            uint32_t pa1 = pack_h(s[2 * kc][2],     s[2 * kc][3]);
            uint32_t pa2 = pack_h(s[2 * kc + 1][0], s[2 * kc + 1][1]);
            uint32_t pa3 = pack_h(s[2 * kc + 1][2], s[2 * kc + 1][3]);
            const int kr = kc * 16 + vkr;
            #pragma unroll
            for (int nf2 = 0; nf2 < 4; nf2++) {
                uint32_t off = (uint32_t)(kr * 128 +
                               (((nf2 * 2 + vdc) ^ (kr & 7)) << 4));
                uint32_t v0, v1, v2, v3;
                LDSM4T(v0, v1, v2, v3, kb + A_V + off);
                MMA_F16(o[nf2 * 2],     pa0, pa1, pa2, pa3, v0, v1);
                MMA_F16(o[nf2 * 2 + 1], pa0, pa1, pa2, pa3, v2, v3);
            }
        }
    }

    // ---- final row-sum reduce (deferred), normalize + write fp16 ----
    lsum[0] += __shfl_xor_sync(0xffffffffu, lsum[0], 1);
    lsum[0] += __shfl_xor_sync(0xffffffffu, lsum[0], 2);
    lsum[1] += __shfl_xor_sync(0xffffffffu, lsum[1], 1);
    lsum[1] += __shfl_xor_sync(0xffffffffu, lsum[1], 2);
    const float inv0 = 1.f / lsum[0], inv1 = 1.f / lsum[1];
    const size_t gr = (size_t)(b * SEQ + qt * 128 + w * 16 + (lane >> 2));
    const int colb = h * HD + (lane & 3) * 2;
    #pragma unroll
    for (int nf = 0; nf < 8; nf++) {
        const int col = colb + nf * 8;
        *(uint32_t*)&outa[gr * DIM + col] = pack_h(o[nf][0] * inv0, o[nf][1] * inv0);
        *(uint32_t*)&outa[(gr + 8) * DIM + col] = pack_h(o[nf][2] * inv1, o[nf][3] * inv1);
    }
}

// =============================== launch ====================================
extern "C" void kernel_launch(void* const* d_in, const int* in_sizes, int n_in,
                              void* d_out, int out_size)
{
    const float* x      = (const float*)d_in[0];
    const float* W_attn = (const float*)d_in[1];
    const float* b_attn = (const float*)d_in[2];
    const float* W_proj = (const float*)d_in[3];
    const float* b_proj = (const float*)d_in[4];
    float* out = (float*)d_out;

    __half *qkv16, *x16, *a16, *w1, *w2;
    cudaGetSymbolAddress((void**)&qkv16, g_qkv16);
    cudaGetSymbolAddress((void**)&x16, g_x16);
    cudaGetSymbolAddress((void**)&a16, g_a16);
    cudaGetSymbolAddress((void**)&w1, g_w1);
    cudaGetSymbolAddress((void**)&w2, g_w2);

    static int attrs_set = 0;
    if (!attrs_set) {
        cudaFuncSetAttribute(gemm_mma<0>, cudaFuncAttributeMaxDynamicSharedMemorySize, GEMM_SMEM);
        cudaFuncSetAttribute(gemm_mma<1>, cudaFuncAttributeMaxDynamicSharedMemorySize, GEMM_SMEM);
        cudaFuncSetAttribute(attn_mma, cudaFuncAttributeMaxDynamicSharedMemorySize, ATT_SMEM);
        attrs_set = 1;
    }

    // 1) x -> fp16
    {
        int n4 = MROWS * KTOT / 4;
        cvt_f16<<<(n4 + 255) / 256, 256>>>(x, x16, n4);
    }
    // 2) weights -> transposed fp16
    transpose_f16<<<dim3(N1 / 32, KTOT / 32), dim3(32, 8)>>>(W_attn, w1, KTOT, N1);
    transpose_f16<<<dim3(N2 / 32, KTOT / 32), dim3(32, 8)>>>(W_proj, w2, KTOT, N2);
    // 3) qkv GEMM (fp16 out)
    gemm_mma<1><<<dim3(N1 / 128, MROWS / 128), 256, GEMM_SMEM>>>(
        x16, w1, b_attn, nullptr, qkv16, N1);
    // 4) attention
    attn_mma<<<dim3(SEQ / 128, NH, BATCH), 256, ATT_SMEM>>>(qkv16, a16);
    // 5) out GEMM (fp32 out)
    gemm_mma<0><<<dim3(N2 / 128, MROWS / 128), 256, GEMM_SMEM>>>(
        a16, w2, b_proj, out, nullptr, N2);
}